// round 1
// baseline (speedup 1.0000x reference)
#include <cuda_runtime.h>

#define BB 2
#define TT 512
#define CC 128
#define C2 256
#define HS 64
#define TJ 16

// scratch (no allocations allowed)
__device__ float g_K[BB*TT*CC];
__device__ float g_Q[BB*TT*CC];
__device__ float g_V[BB*TT*HS];
__device__ float g_S[(size_t)BB*TT*TT];

// ---------------------------------------------------------------------------
// Kernel 1: K = x @ W1[0:C], Q = x @ W1[C:2C], V = x @ Wv + bv
// ---------------------------------------------------------------------------
__global__ void kqv_kernel(const float* __restrict__ x,
                           const float* __restrict__ W1,
                           const float* __restrict__ Wv,
                           const float* __restrict__ bv) {
    int row = blockIdx.x;          // 0 .. B*T-1
    int h = threadIdx.x;           // 0 .. 127
    __shared__ float xs[CC];
    xs[h] = x[row*CC + h];
    __syncthreads();

    float ak = 0.f, aq = 0.f;
#pragma unroll 8
    for (int d = 0; d < CC; d++) {
        float xv = xs[d];
        ak = fmaf(xv, W1[d*CC + h],        ak);
        aq = fmaf(xv, W1[(CC + d)*CC + h], aq);
    }
    g_K[row*CC + h] = ak;
    g_Q[row*CC + h] = aq;

    if (h < HS) {
        float av = bv[h];
#pragma unroll 8
        for (int d = 0; d < CC; d++)
            av = fmaf(xs[d], Wv[d*HS + h], av);
        g_V[row*HS + h] = av;
    }
}

// ---------------------------------------------------------------------------
// Kernel 2: fused P-GEMM + gelu + W2 dot -> scores (lower triangle only)
//   block = (i, j-tile of 16), 128 threads, thread h owns hidden column h
// ---------------------------------------------------------------------------
__global__ void score_kernel(const float* __restrict__ pd,
                             const float* __restrict__ W1,
                             const float* __restrict__ b1,
                             const float* __restrict__ W2,
                             const float* __restrict__ b2) {
    int i = blockIdx.x;
    int jbase = blockIdx.y * TJ;
    if (jbase > i) return;                 // above diagonal: nothing to do

    int h    = threadIdx.x;                // 0..127
    int lane = h & 31;
    int wid  = h >> 5;

    __shared__ float a2s[TJ][C2];          // 16 KB pd tile
    __shared__ float part[4][2*TJ];

    // stage pd[i, jbase:jbase+16, :] (contiguous 16*256 floats)
    {
        float4*       dst4 = (float4*)&a2s[0][0];
        const float4* src4 = (const float4*)(pd + ((size_t)i*TT + jbase)*C2);
#pragma unroll
        for (int t = h; t < TJ*C2/4; t += 128) dst4[t] = src4[t];
    }
    __syncthreads();

    // P tile: 16 rows x (my column h), dot over 256
    float acc[TJ];
#pragma unroll
    for (int jj = 0; jj < TJ; jj++) acc[jj] = 0.f;

#pragma unroll 4
    for (int d = 0; d < C2; d++) {
        float w = W1[d*CC + h];
#pragma unroll
        for (int jj = 0; jj < TJ; jj++)
            acc[jj] = fmaf(a2s[jj][d], w, acc[jj]);
    }

    float bh = b1[h];
    float w2 = W2[h];

#pragma unroll
    for (int b = 0; b < BB; b++) {
        float qv = g_Q[((size_t)b*TT + i)*CC + h] + bh;
#pragma unroll
        for (int jj = 0; jj < TJ; jj++) {
            float pre = acc[jj] + qv + g_K[((size_t)b*TT + jbase + jj)*CC + h];
            // exact gelu: 0.5*x*(1+erf(x/sqrt(2)))
            float gl = 0.5f * pre * (1.f + erff(pre * 0.70710678118654752f));
            float c  = gl * w2;
#pragma unroll
            for (int off = 16; off; off >>= 1)
                c += __shfl_xor_sync(0xffffffffu, c, off);
            if (lane == 0) part[wid][b*TJ + jj] = c;
        }
    }
    __syncthreads();

    if (h < BB*TJ) {
        float s = part[0][h] + part[1][h] + part[2][h] + part[3][h] + b2[0];
        int b  = h / TJ;
        int jj = h % TJ;
        int j  = jbase + jj;
        if (j <= i)
            g_S[((size_t)b*TT + i)*TT + j] = s;
    }
}

// ---------------------------------------------------------------------------
// Kernel 3: causal softmax (scaled) + wei @ V
// ---------------------------------------------------------------------------
__global__ void softmax_av_kernel(float* __restrict__ out) {
    int bi = blockIdx.x;                   // 0 .. B*T-1
    int b  = bi / TT;
    int i  = bi % TT;
    int t  = threadIdx.x;                  // 0..127
    int n  = i + 1;

    __shared__ float p[TT];
    __shared__ float red[128];
    const float scale = 0.088388347648318447f;   // 128^-0.5

    const float* srow = &g_S[((size_t)b*TT + i)*TT];

    float m = -1e30f;
    for (int j = t; j < n; j += 128) m = fmaxf(m, srow[j] * scale);
    red[t] = m; __syncthreads();
    for (int s = 64; s; s >>= 1) { if (t < s) red[t] = fmaxf(red[t], red[t+s]); __syncthreads(); }
    m = red[0]; __syncthreads();

    float sum = 0.f;
    for (int j = t; j < n; j += 128) {
        float e = expf(srow[j] * scale - m);
        p[j] = e;
        sum += e;
    }
    red[t] = sum; __syncthreads();
    for (int s = 64; s; s >>= 1) { if (t < s) red[t] += red[t+s]; __syncthreads(); }
    float inv = 1.f / red[0];

    if (t < HS) {
        float acc = 0.f;
        for (int j = 0; j < n; j++)
            acc = fmaf(p[j], g_V[((size_t)b*TT + j)*HS + t], acc);
        out[((size_t)b*TT + i)*HS + t] = acc * inv;
    }
}

// ---------------------------------------------------------------------------
extern "C" void kernel_launch(void* const* d_in, const int* in_sizes, int n_in,
                              void* d_out, int out_size) {
    const float* x   = (const float*)d_in[0];
    // d_in[1] = pos_emb (unused by reference)
    const float* pd  = (const float*)d_in[2];
    const float* W1  = (const float*)d_in[3];
    const float* b1  = (const float*)d_in[4];
    const float* W2  = (const float*)d_in[5];
    const float* b2  = (const float*)d_in[6];
    const float* Wv  = (const float*)d_in[7];
    const float* bv  = (const float*)d_in[8];
    float* out = (float*)d_out;

    kqv_kernel<<<BB*TT, 128>>>(x, W1, Wv, bv);
    score_kernel<<<dim3(TT, TT/TJ), 128>>>(pd, W1, b1, W2, b2);
    softmax_av_kernel<<<BB*TT, 128>>>(out);
}